// round 14
// baseline (speedup 1.0000x reference)
#include <cuda_runtime.h>
#include <cstdint>
#include <math.h>

#define B_ 2
#define H_ 16
#define S_ 2048
#define D_ 72
#define BHS_ (B_*H_*S_)
#define L2E 1.4426950408889634f

// TMEM columns: TSP0 0..63, TSP1 64..127, TO 128..199  (alloc 256)
#define TO 128

#define QBYTES 36864   // 128r x 72c fp32 SW32
#define KB     18432   // 64r x 72c fp32 SW32  /  72r x 64c fp32 SW128 (V^T)
#define QW     9216
#define KW     4608

#define PREP_BLOCKS 8192   // BHS_*32/256
#define VPREP_BLOCKS 1024

#if !defined(__CUDA_ARCH__) || defined(__CUDA_ARCH_FEAT_SM103_ALL)
#define TC_OK 1
#else
#define TC_OK 0
#endif

__device__ float g_sdot[BHS_];                             // q.k self dot per row
__device__ __align__(1024) uint32_t g_qsw[32*16*QW];       // pre-swizzled tf32 Q tiles (SW32)
__device__ __align__(1024) uint32_t g_ksw[32*32*KW];       // pre-swizzled tf32 K tiles (SW32)
__device__ __align__(1024) uint32_t g_vsw[32*32*KW];       // pre-swizzled tf32 V^T tiles (SW128)

// ---------------- helpers ----------------
__device__ __forceinline__ uint32_t s2u(const void* p){ uint32_t a;
  asm("{ .reg .u64 t; cvta.to.shared.u64 t, %1; cvt.u32.u64 %0, t; }" : "=r"(a) : "l"(p)); return a; }
__device__ __forceinline__ float ex2f_(float x){ float y;
  asm("ex2.approx.ftz.f32 %0, %1;" : "=f"(y) : "f"(x)); return y; }
__device__ __forceinline__ uint32_t f2tf(float x){ uint32_t u;
  asm("cvt.rna.tf32.f32 %0, %1;" : "=r"(u) : "f"(x)); return u; }

#define SWZ128(x) ((x) ^ (((x)>>3) & 0x70))
#define SWZ32(x)  ((x) ^ (((x)>>3) & 0x10))

#if TC_OK
__device__ __forceinline__ uint32_t elect1(){ uint32_t e;
  asm volatile("{\n\t.reg .pred p;\n\telect.sync _|p, 0xFFFFFFFF;\n\tselp.b32 %0, 1, 0, p;\n\t}" : "=r"(e)); return e; }
__device__ __forceinline__ uint64_t mkdesc128(uint32_t addr){
  const uint64_t base = (uint64_t(2)<<61) | (uint64_t(1)<<46) | (uint64_t(64)<<32) | (uint64_t(1)<<16);
  return base | ((uint64_t)(addr >> 4) & 0x3FFF);
}
__device__ __forceinline__ uint64_t mkdesc32(uint32_t addr){
  const uint64_t base = (uint64_t(6)<<61) | (uint64_t(1)<<46) | (uint64_t(16)<<32) | (uint64_t(1)<<16);
  return base | ((uint64_t)(addr >> 4) & 0x3FFF);
}
__device__ __forceinline__ void mma_tf32_ts(uint32_t d, uint32_t a, uint64_t bd, uint32_t idesc, uint32_t en){
  asm volatile("{\n\t.reg .pred p;\n\tsetp.ne.u32 p, %4, 0;\n\t"
    "tcgen05.mma.cta_group::1.kind::tf32 [%0], [%1], %2, %3, {%5,%5,%5,%5}, p;\n\t}"
    :: "r"(d), "r"(a), "l"(bd), "r"(idesc), "r"(en), "r"(0u) : "memory");
}
__device__ __forceinline__ void mma_tf32_ss(uint32_t d, uint64_t ad, uint64_t bd, uint32_t idesc, uint32_t en){
  asm volatile("{\n\t.reg .pred p;\n\tsetp.ne.u32 p, %4, 0;\n\t"
    "tcgen05.mma.cta_group::1.kind::tf32 [%0], %1, %2, %3, {%5,%5,%5,%5}, p;\n\t}"
    :: "r"(d), "l"(ad), "l"(bd), "r"(idesc), "r"(en), "r"(0u) : "memory");
}
__device__ __forceinline__ void bulk_g2s(uint32_t dst, const void* src, uint32_t bytes, uint32_t mbar){
  asm volatile("cp.async.bulk.shared::cluster.global.mbarrier::complete_tx::bytes [%0], [%1], %2, [%3];"
    :: "r"(dst), "l"(src), "r"(bytes), "r"(mbar) : "memory");
}

#define TC_ALLOC(sa,n)  asm volatile("tcgen05.alloc.cta_group::1.sync.aligned.shared::cta.b32 [%0], %1;" :: "r"(sa), "r"(n) : "memory")
#define TC_DEALLOC(tb,n) asm volatile("tcgen05.dealloc.cta_group::1.sync.aligned.b32 %0, %1;" :: "r"(tb), "r"(n))
#define TC_RELINQ()     asm volatile("tcgen05.relinquish_alloc_permit.cta_group::1.sync.aligned;")
#define TC_COMMIT(mb)   asm volatile("tcgen05.commit.cta_group::1.mbarrier::arrive::one.shared::cluster.b64 [%0];" :: "r"(mb) : "memory")
#define TC_WAIT_LD()    asm volatile("tcgen05.wait::ld.sync.aligned;" ::: "memory")
#define TC_WAIT_ST()    asm volatile("tcgen05.wait::st.sync.aligned;" ::: "memory")
#define TC_FENCE_B()    asm volatile("tcgen05.fence::before_thread_sync;" ::: "memory")
#define TC_FENCE_A()    asm volatile("tcgen05.fence::after_thread_sync;" ::: "memory")
#define MB_INIT(mb,c)   asm volatile("mbarrier.init.shared.b64 [%0], %1;" :: "r"(mb), "r"(c) : "memory")
#define MB_EXPECT_TX(mb,n) asm volatile("mbarrier.arrive.expect_tx.shared.b64 _, [%0], %1;" :: "r"(mb), "r"(n) : "memory")
#define MB_ARRIVE(mb)   asm volatile("mbarrier.arrive.shared.b64 _, [%0];" :: "r"(mb) : "memory")

#define MB_WAIT(mbar, par) do { \
  uint32_t _m = (mbar); uint32_t _p = (par); uint32_t _d; \
  asm volatile("{\n\t.reg .pred p;\n\t" \
    "mbarrier.try_wait.parity.acquire.cta.shared::cta.b64 p, [%1], %2;\n\t" \
    "selp.b32 %0, 1, 0, p;\n\t}" : "=r"(_d) : "r"(_m), "r"(_p) : "memory"); \
  if (!_d) { \
    asm volatile("{\n\t.reg .pred P1;\n\t" \
      "WL_%=:\n\t" \
      "mbarrier.try_wait.parity.acquire.cta.shared::cta.b64 P1, [%0], %1, 0x989680;\n\t" \
      "@P1 bra.uni WD_%=;\n\tbra.uni WL_%=;\n\tWD_%=:\n\t}" \
      :: "r"(_m), "r"(_p) : "memory"); \
  } \
} while(0)

#define LDTM_X32(r,a) \
  asm volatile("tcgen05.ld.sync.aligned.32x32b.x32.b32 " \
    "{%0,%1,%2,%3,%4,%5,%6,%7,%8,%9,%10,%11,%12,%13,%14,%15," \
    "%16,%17,%18,%19,%20,%21,%22,%23,%24,%25,%26,%27,%28,%29,%30,%31}, [%32];" \
    : "=r"((r)[0]),"=r"((r)[1]),"=r"((r)[2]),"=r"((r)[3]),"=r"((r)[4]),"=r"((r)[5]),"=r"((r)[6]),"=r"((r)[7]), \
      "=r"((r)[8]),"=r"((r)[9]),"=r"((r)[10]),"=r"((r)[11]),"=r"((r)[12]),"=r"((r)[13]),"=r"((r)[14]),"=r"((r)[15]), \
      "=r"((r)[16]),"=r"((r)[17]),"=r"((r)[18]),"=r"((r)[19]),"=r"((r)[20]),"=r"((r)[21]),"=r"((r)[22]),"=r"((r)[23]), \
      "=r"((r)[24]),"=r"((r)[25]),"=r"((r)[26]),"=r"((r)[27]),"=r"((r)[28]),"=r"((r)[29]),"=r"((r)[30]),"=r"((r)[31]) \
    : "r"(a))

#define LDTM_X8(r,a) \
  asm volatile("tcgen05.ld.sync.aligned.32x32b.x8.b32 {%0,%1,%2,%3,%4,%5,%6,%7}, [%8];" \
    : "=r"((r)[0]),"=r"((r)[1]),"=r"((r)[2]),"=r"((r)[3]),"=r"((r)[4]),"=r"((r)[5]),"=r"((r)[6]),"=r"((r)[7]) \
    : "r"(a))

#define STTM_X32(a,r) \
  asm volatile("tcgen05.st.sync.aligned.32x32b.x32.b32 [%0], " \
    "{%1,%2,%3,%4,%5,%6,%7,%8,%9,%10,%11,%12,%13,%14,%15,%16," \
    "%17,%18,%19,%20,%21,%22,%23,%24,%25,%26,%27,%28,%29,%30,%31,%32};" \
    :: "r"(a), \
       "r"((r)[0]),"r"((r)[1]),"r"((r)[2]),"r"((r)[3]),"r"((r)[4]),"r"((r)[5]),"r"((r)[6]),"r"((r)[7]), \
       "r"((r)[8]),"r"((r)[9]),"r"((r)[10]),"r"((r)[11]),"r"((r)[12]),"r"((r)[13]),"r"((r)[14]),"r"((r)[15]), \
       "r"((r)[16]),"r"((r)[17]),"r"((r)[18]),"r"((r)[19]),"r"((r)[20]),"r"((r)[21]),"r"((r)[22]),"r"((r)[23]), \
       "r"((r)[24]),"r"((r)[25]),"r"((r)[26]),"r"((r)[27]),"r"((r)[28]),"r"((r)[29]),"r"((r)[30]),"r"((r)[31]) \
    : "memory")
#endif // TC_OK

// idesc: f32 D (bit4), tf32 A (2<<7), tf32 B (2<<10), N>>3 @17, M>>4 @24
#define IDESC_QK (0x10u | (2u<<7) | (2u<<10) | (8u<<17) | (8u<<24))   // N=64
#define IDESC_PV (0x10u | (2u<<7) | (2u<<10) | (9u<<17) | (8u<<24))   // N=72

// ---------------------------------------------------------------------------
// Kernel 1 (merged): blocks [0, PREP_BLOCKS) do RoPE+normalize -> Q/K swizzled
// tiles + self dot; blocks [PREP_BLOCKS, +VPREP_BLOCKS) do V^T swizzled tiles.
// Fast __sincosf: |theta| <= ~32 rad, abs err ~1e-5, well inside error budget.
// ---------------------------------------------------------------------------
__global__ void prep_all(const float* __restrict__ q, const float* __restrict__ k,
                         const float* __restrict__ v,
                         const float* __restrict__ pos, const float* __restrict__ pos_orig,
                         const float* __restrict__ tim, const float* __restrict__ freqs,
                         const float* __restrict__ t_freqs, const float* __restrict__ scale)
{
    __shared__ float sv[64*77];
    int tid = threadIdx.x;

    if (blockIdx.x >= PREP_BLOCKS) {
        // ---- V^T pre-swizzle ----
        int bid2 = blockIdx.x - PREP_BLOCKS;
        int bh = bid2 >> 5, kt = bid2 & 31;
        const float* vb = v + ((size_t)bh*S_ + kt*64)*D_;
        for (int i = tid; i < 64*D_; i += 256) {
            int r = i / D_, d = i - r*D_;
            sv[r*77 + d] = vb[i];
        }
        __syncthreads();
        uint32_t tb_ = (uint32_t)(bh*32 + kt) * KW;
        for (int i = tid; i < 72*64; i += 256) {
            int d = i >> 6, r = i & 63;
            uint32_t vo = (uint32_t)((d>>3) + (r>>5)*9)*1024u + (uint32_t)(d&7)*128u + (uint32_t)(r&31)*4u;
            g_vsw[tb_ + (SWZ128(vo) >> 2)] = f2tf(sv[r*77 + d]);
        }
        return;
    }

    // ---- RoPE + normalize ----
    int gid  = blockIdx.x*256 + tid;
    int wid  = gid >> 5;
    int lane = gid & 31;
    int s = wid & (S_-1);
    int h = (wid >> 11) & (H_-1);
    int b = wid >> 15;
    int bh = wid >> 11;
    int bs = b*S_ + s;

    float px  = pos[bs*2+0]*2.f - 1.f;
    float py  = pos[bs*2+1]*2.f - 1.f;
    float pxo = pos_orig[bs*2+0]*2.f - 1.f;
    float pyo = pos_orig[bs*2+1]*2.f - 1.f;
    float tm  = tim[bs];

    float cv = 1.f, svv = 0.f;
    if (lane < 30) {
        int m = lane / 6, j = lane % 6;
        float th;
        if      (m == 0) th = pyo * freqs[96 + h*6 + j];
        else if (m == 1) th = py  * freqs[96 + h*6 + j];
        else if (m == 2) th = pxo * freqs[h*6 + j];
        else if (m == 3) th = px  * freqs[h*6 + j];
        else             th = tm  * t_freqs[h*6 + j];
        __sincosf(th, &svv, &cv);
    }
    int idxA = (lane < 30) ? lane : (lane - 30);
    int idxB = (lane < 28) ? (lane + 2) : 0;
    float cA = __shfl_sync(0xffffffffu, cv, idxA);
    float sA = __shfl_sync(0xffffffffu, svv, idxA);
    float cB = __shfl_sync(0xffffffffu, cv, idxB);
    float sB = __shfl_sync(0xffffffffu, svv, idxB);

    float fac_scale = sqrtf(scale[h]);
    size_t rowoff = (size_t)wid * D_;

    float qa, qb_, qc, ka, kb_, kc;
    #pragma unroll
    for (int which = 0; which < 2; which++) {
        const float* xr = (which == 0 ? q : k) + rowoff;

        float xa = xr[lane];
        float xb = xr[lane+32];
        float xc = (lane < 8) ? xr[lane+64] : 0.f;
        float xpa = (lane < 30) ? xr[lane+30] : xr[lane-30];
        float xpb = (lane < 28) ? xr[lane+2]  : 0.f;

        float oa = (lane < 30) ? (xa*cA - xpa*sA) : (xa*cA + xpa*sA);
        float ob = (lane < 28) ? (xb*cB + xpb*sB) : xb;
        float oc = xc;

        float ss = oa*oa + ob*ob + oc*oc;
        #pragma unroll
        for (int mm = 16; mm >= 1; mm >>= 1)
            ss += __shfl_xor_sync(0xffffffffu, ss, mm);
        float fac = fac_scale * rsqrtf(ss + 1e-6f);

        if (which == 0) { qa = oa*fac; qb_ = ob*fac; qc = oc*fac; }
        else            { ka = oa*fac; kb_ = ob*fac; kc = oc*fac; }
    }

    // Q SW32 tile: 128 rows, atom = (r>>3) + (d>>3)*16
    {
        int qt = s >> 7, r = s & 127;
        uint32_t tb_ = (uint32_t)(bh*16 + qt) * QW;
        #pragma unroll
        for (int seg = 0; seg < 3; seg++) {
            int d = lane + seg*32;
            if (seg == 2 && lane >= 8) break;
            float val = (seg == 0) ? qa : (seg == 1) ? qb_ : qc;
            uint32_t o = (uint32_t)((r>>3) + (d>>3)*16)*256u + (uint32_t)(r&7)*32u + (uint32_t)(d&7)*4u;
            g_qsw[tb_ + (SWZ32(o) >> 2)] = f2tf(val);
        }
    }
    // K SW32 tile: 64 rows, atom = (r>>3) + (d>>3)*8
    {
        int kt = s >> 6, r = s & 63;
        uint32_t tb_ = (uint32_t)(bh*32 + kt) * KW;
        #pragma unroll
        for (int seg = 0; seg < 3; seg++) {
            int d = lane + seg*32;
            if (seg == 2 && lane >= 8) break;
            float val = (seg == 0) ? ka : (seg == 1) ? kb_ : kc;
            uint32_t o = (uint32_t)((r>>3) + (d>>3)*8)*256u + (uint32_t)(r&7)*32u + (uint32_t)(d&7)*4u;
            g_ksw[tb_ + (SWZ32(o) >> 2)] = f2tf(val);
        }
    }

    float sd = qa*ka + qb_*kb_ + qc*kc;
    #pragma unroll
    for (int mm = 16; mm >= 1; mm >>= 1)
        sd += __shfl_xor_sync(0xffffffffu, sd, mm);
    if (lane == 0) g_sdot[wid] = sd;
}

// no-op alignment kernel (container-safe 4-launch layout)
__global__ void dummy_kernel() {}

// ---------------------------------------------------------------------------
// Kernel 2: pipelined tcgen05 tf32 flash attention; K and V double-buffered.
// Heavy q-tiles scheduled first (qt = 15 - blockIdx.x) to shrink the tail.
// ---------------------------------------------------------------------------
__global__ void __launch_bounds__(288, 2)
attn_tc(const float* __restrict__ v, float* __restrict__ out)
{
#if TC_OK
    int qt  = (S_/128 - 1) - blockIdx.x;   // heavy tiles (qt=15, ktn=17) first
    int bh  = blockIdx.y;
    int tid = threadIdx.x;
    int q0  = qt*128;
    float* obase = out + (size_t)bh*S_*D_;

    if (qt < 4) {
        for (int i = tid; i < 128*D_; i += 288) obase[q0*D_ + i] = 0.f;
        return;
    }

    extern __shared__ char dynsm[];
    uint32_t sbase = (s2u(dynsm) + 1023u) & ~1023u;
    uint32_t sQ = sbase;
    uint32_t sK[2] = { sQ + QBYTES, sQ + QBYTES + KB };
    uint32_t sV[2] = { sQ + QBYTES + 2*KB, sQ + QBYTES + 3*KB };
    char* smraw = dynsm + (sbase - s2u(dynsm));
    float* ost = (float*)(smraw);              // Q region reused at end
    float* vst = (float*)(smraw + QBYTES);     // K region reused at end

    __shared__ __align__(16) uint32_t s_tmem[4];
    __shared__ __align__(16) uint64_t s_mbar[12];
    __shared__ float ssum[128], sinvv[128], sselfp[128];
    uint32_t mbF[2] = { s2u(&s_mbar[0]), s2u(&s_mbar[1]) };
    uint32_t mbV[2] = { s2u(&s_mbar[2]), s2u(&s_mbar[3]) };
    uint32_t mb1[2] = { s2u(&s_mbar[4]), s2u(&s_mbar[5]) };
    uint32_t mb2[2] = { s2u(&s_mbar[6]), s2u(&s_mbar[7]) };
    uint32_t eb[2]  = { s2u(&s_mbar[8]), s2u(&s_mbar[9]) };
    uint32_t fb     = s2u(&s_mbar[10]);
    int wrp = tid >> 5;

    if (wrp == 8) TC_ALLOC(s2u(s_tmem), 256);
    if (tid == 0) {
        MB_INIT(mbF[0],1); MB_INIT(mbF[1],1);
        MB_INIT(mbV[0],1); MB_INIT(mbV[1],1);
        MB_INIT(mb1[0],1); MB_INIT(mb1[1],1);
        MB_INIT(mb2[0],1); MB_INIT(mb2[1],1);
        MB_INIT(eb[0],256); MB_INIT(eb[1],256);
        MB_INIT(fb,1);
    }
    __syncthreads();
    uint32_t tb;
    asm volatile("ld.shared.b32 %0, [%1];" : "=r"(tb) : "r"(s2u(s_tmem)));

    const uint32_t* ktiles = g_ksw + (size_t)(bh*32) * KW;
    const uint32_t* vtiles = g_vsw + (size_t)(bh*32) * KW;
    const uint32_t* qtile  = g_qsw + (size_t)(bh*16 + qt) * QW;

    int ktn = (qt >= 8) ? 17 : (2*qt + 2);

    if (wrp == 8) {
        if (elect1()) {
            uint64_t adesc    = mkdesc32(sQ);
            uint64_t kdesc[2] = { mkdesc32(sK[0]), mkdesc32(sK[1]) };
            uint64_t vdesc[2] = { mkdesc128(sV[0]), mkdesc128(sV[1]) };
            int phF[2] = {0,0}, phV[2] = {0,0}, ph1m[2] = {0,0}, ph2[2] = {0,0};
            int ebph[2] = {0,0};

            MB_EXPECT_TX(mbF[0], QBYTES + KB);
            bulk_g2s(sQ,    qtile,  QBYTES, mbF[0]);
            bulk_g2s(sK[0], ktiles, KB,     mbF[0]);
            if (ktn > 1) { MB_EXPECT_TX(mbF[1], KB); bulk_g2s(sK[1], ktiles + KW, KB, mbF[1]); }
            MB_EXPECT_TX(mbV[0], KB);
            bulk_g2s(sV[0], vtiles, KB, mbV[0]);
            if (ktn > 1) { MB_EXPECT_TX(mbV[1], KB); bulk_g2s(sV[1], vtiles + KW, KB, mbV[1]); }

            MB_WAIT(mbF[0], 0); phF[0] = 1;
            TC_FENCE_A();
            #pragma unroll
            for (int s8 = 0; s8 < 9; s8++)
                mma_tf32_ss(tb + 0, adesc + (uint64_t)s8*256, kdesc[0] + (uint64_t)s8*128, IDESC_QK, s8 > 0);
            TC_COMMIT(mb1[0]);

            for (int t = 0; t < ktn; t++) {
                int b = t & 1, nb = b ^ 1;

                if (t+1 < ktn) {
                    MB_WAIT(mbF[nb], phF[nb]); phF[nb] ^= 1;
                    TC_FENCE_A();
                    #pragma unroll
                    for (int s8 = 0; s8 < 9; s8++)
                        mma_tf32_ss(tb + nb*64, adesc + (uint64_t)s8*256, kdesc[nb] + (uint64_t)s8*128, IDESC_QK, s8 > 0);
                    TC_COMMIT(mb1[nb]);
                }
                if (t+2 < ktn) {                       // K(t+2) -> sK[b]
                    MB_WAIT(mb1[b], ph1m[b]); ph1m[b] ^= 1;
                    MB_EXPECT_TX(mbF[b], KB);
                    bulk_g2s(sK[b], ktiles + (size_t)(t+2)*KW, KB, mbF[b]);
                }

                MB_WAIT(eb[b], ebph[b]); ebph[b] ^= 1;
                MB_WAIT(mbV[b], phV[b]); phV[b] ^= 1;
                TC_FENCE_A();
                #pragma unroll
                for (int s8 = 0; s8 < 8; s8++)
                    mma_tf32_ts(tb + TO, tb + b*64 + s8*8, vdesc[b] + (uint64_t)((s8>>2)*576 + (s8&3)*2), IDESC_PV, (t > 0) || (s8 > 0));
                TC_COMMIT(mb2[b]);

                if (t+2 < ktn) {                       // V(t+2) -> sV[b]
                    MB_WAIT(mb2[b], ph2[b]); ph2[b] ^= 1;
                    MB_EXPECT_TX(mbV[b], KB);
                    bulk_g2s(sV[b], vtiles + (size_t)(t+2)*KW, KB, mbV[b]);
                }
            }
            int lb = (ktn-1) & 1;
            MB_WAIT(mb2[lb], ph2[lb]);
            MB_ARRIVE(fb);
        }
    } else {
        int row  = tid & 127;
        int half = tid >> 7;
        uint32_t colofs = (uint32_t)half * 32u;
        uint32_t woff = ((uint32_t)row >> 5) << 21;
        int q = q0 + row;
        int qeff = (q < 576) ? -1 : ((q < 1088) ? q : 0x7fffffff);
        float sum = 0.f, selfp = 0.f;
        if (q >= 1088 && half == 0) {
            selfp = ex2f_((g_sdot[(size_t)bh*S_ + q] - 1.5f)*L2E);
            sum = selfp;
        }
        int ph1_[2] = {0,0};

        for (int t = 0; t < ktn; t++) {
            int b = t & 1;
            MB_WAIT(mb1[b], ph1_[b]); ph1_[b] ^= 1;
            TC_FENCE_A();
            uint32_t sr[32];
            LDTM_X32(sr, tb + b*64 + colofs);
            TC_WAIT_LD();
            int k0 = t*64 + (int)colofs;
            float lsum = 0.f;
            #pragma unroll
            for (int j = 0; j < 32; j++) {
                float sc = __uint_as_float(sr[j]);
                float p  = (k0 + j <= qeff) ? ex2f_(fmaf(sc, L2E, -1.5f*L2E)) : 0.f;
                sr[j] = f2tf(p);
                lsum += __uint_as_float(sr[j]);
            }
            sum += lsum;
            STTM_X32(tb + b*64 + colofs + woff, sr);
            TC_WAIT_ST();
            TC_FENCE_B();
            MB_ARRIVE(eb[b]);
        }
        if (half == 1) ssum[row] = sum;
        else { sinvv[row] = sum; sselfp[row] = selfp; }
    }

    MB_WAIT(fb, 0);
    TC_FENCE_A();
    __syncthreads();

    {
        const float* vb = v + ((size_t)bh*S_ + q0)*D_;
        for (int i = tid; i < 128*D_; i += 288) vst[i] = vb[i];
    }
    __syncthreads();

    if (tid < 128) {
        int q = q0 + tid;
        float tot = sinvv[tid] + ssum[tid];
        if (q < 576) { sinvv[tid] = 0.f; sselfp[tid] = 0.f; }
        else         { sinvv[tid] = 1.f / tot; }
    }
    __syncthreads();

    if (tid < 256) {
        int row  = tid & 127;
        int half = tid >> 7;
        float inv = sinvv[row], sp = sselfp[row];
        float* op = ost + row*D_;
        const float* vp = vst + row*D_;
        if (half == 0) {
            uint32_t o1[32], o3[8];
            LDTM_X32(o1, tb + TO);
            LDTM_X8 (o3, tb + TO + 64);
            TC_WAIT_LD();
            #pragma unroll
            for (int d = 0; d < 32; d++) op[d]    = (__uint_as_float(o1[d]) + sp*vp[d])    * inv;
            #pragma unroll
            for (int d = 0; d < 8; d++)  op[64+d] = (__uint_as_float(o3[d]) + sp*vp[64+d]) * inv;
        } else {
            uint32_t o2[32];
            LDTM_X32(o2, tb + TO + 32);
            TC_WAIT_LD();
            #pragma unroll
            for (int d = 0; d < 32; d++) op[32+d] = (__uint_as_float(o2[d]) + sp*vp[32+d]) * inv;
        }
    }
    __syncthreads();

    for (int i = tid; i < 128*D_; i += 288) obase[q0*D_ + i] = ost[i];

    __syncthreads();
    if (wrp == 8) {
        TC_RELINQ();
        TC_DEALLOC(tb, 256);
    }
#endif
}

extern "C" void kernel_launch(void* const* d_in, const int* in_sizes, int n_in,
                              void* d_out, int out_size)
{
    const float* q        = (const float*)d_in[0];
    const float* k        = (const float*)d_in[1];
    const float* v        = (const float*)d_in[2];
    const float* pos      = (const float*)d_in[3];
    const float* pos_orig = (const float*)d_in[4];
    const float* tim      = (const float*)d_in[5];
    const float* freqs    = (const float*)d_in[6];
    const float* t_freqs  = (const float*)d_in[7];
    const float* scale    = (const float*)d_in[8];
    float* out = (float*)d_out;

    const int smem_bytes = QBYTES + 4*KB + 1024;   // 111616
    cudaFuncSetAttribute(attn_tc, cudaFuncAttributeMaxDynamicSharedMemorySize, smem_bytes);

    // Known-container-safe 4-launch layout.
    prep_all<<<PREP_BLOCKS + VPREP_BLOCKS, 256>>>(q, k, v, pos, pos_orig, tim, freqs, t_freqs, scale);
    dummy_kernel<<<1, 32>>>();

    dim3 grid(S_/128, B_*H_);
    attn_tc<<<grid, 288, smem_bytes>>>(v, out);
    dummy_kernel<<<1, 32>>>();
}

// round 15
// speedup vs baseline: 1.0298x; 1.0298x over previous
#include <cuda_runtime.h>
#include <cstdint>
#include <math.h>

#define B_ 2
#define H_ 16
#define S_ 2048
#define D_ 72
#define BHS_ (B_*H_*S_)
#define L2E 1.4426950408889634f

// TMEM columns: TSP0 0..63, TSP1 64..127, TO 128..199  (alloc 256)
#define TO 128

#define QBYTES 36864   // 128r x 72c fp32 SW32
#define KB     18432   // 64r x 72c fp32 SW32  /  72r x 64c fp32 SW128 (V^T)
#define QW     9216
#define KW     4608

#define PREP_BLOCKS 8192   // BHS_*32/256
#define VPREP_BLOCKS 1024

#if !defined(__CUDA_ARCH__) || defined(__CUDA_ARCH_FEAT_SM103_ALL)
#define TC_OK 1
#else
#define TC_OK 0
#endif

__device__ float g_sdot[BHS_];                             // q.k self dot per row
__device__ __align__(1024) uint32_t g_qsw[32*16*QW];       // pre-swizzled tf32 Q tiles (SW32)
__device__ __align__(1024) uint32_t g_ksw[32*32*KW];       // pre-swizzled tf32 K tiles (SW32)
__device__ __align__(1024) uint32_t g_vsw[32*32*KW];       // pre-swizzled tf32 V^T tiles (SW128)

// ---------------- helpers ----------------
__device__ __forceinline__ uint32_t s2u(const void* p){ uint32_t a;
  asm("{ .reg .u64 t; cvta.to.shared.u64 t, %1; cvt.u32.u64 %0, t; }" : "=r"(a) : "l"(p)); return a; }
__device__ __forceinline__ float ex2f_(float x){ float y;
  asm("ex2.approx.ftz.f32 %0, %1;" : "=f"(y) : "f"(x)); return y; }
__device__ __forceinline__ uint32_t f2tf(float x){ uint32_t u;
  asm("cvt.rna.tf32.f32 %0, %1;" : "=r"(u) : "f"(x)); return u; }

#define SWZ128(x) ((x) ^ (((x)>>3) & 0x70))
#define SWZ32(x)  ((x) ^ (((x)>>3) & 0x10))

#if TC_OK
__device__ __forceinline__ uint32_t elect1(){ uint32_t e;
  asm volatile("{\n\t.reg .pred p;\n\telect.sync _|p, 0xFFFFFFFF;\n\tselp.b32 %0, 1, 0, p;\n\t}" : "=r"(e)); return e; }
__device__ __forceinline__ uint64_t mkdesc128(uint32_t addr){
  const uint64_t base = (uint64_t(2)<<61) | (uint64_t(1)<<46) | (uint64_t(64)<<32) | (uint64_t(1)<<16);
  return base | ((uint64_t)(addr >> 4) & 0x3FFF);
}
__device__ __forceinline__ uint64_t mkdesc32(uint32_t addr){
  const uint64_t base = (uint64_t(6)<<61) | (uint64_t(1)<<46) | (uint64_t(16)<<32) | (uint64_t(1)<<16);
  return base | ((uint64_t)(addr >> 4) & 0x3FFF);
}
__device__ __forceinline__ void mma_tf32_ts(uint32_t d, uint32_t a, uint64_t bd, uint32_t idesc, uint32_t en){
  asm volatile("{\n\t.reg .pred p;\n\tsetp.ne.u32 p, %4, 0;\n\t"
    "tcgen05.mma.cta_group::1.kind::tf32 [%0], [%1], %2, %3, {%5,%5,%5,%5}, p;\n\t}"
    :: "r"(d), "r"(a), "l"(bd), "r"(idesc), "r"(en), "r"(0u) : "memory");
}
__device__ __forceinline__ void mma_tf32_ss(uint32_t d, uint64_t ad, uint64_t bd, uint32_t idesc, uint32_t en){
  asm volatile("{\n\t.reg .pred p;\n\tsetp.ne.u32 p, %4, 0;\n\t"
    "tcgen05.mma.cta_group::1.kind::tf32 [%0], %1, %2, %3, {%5,%5,%5,%5}, p;\n\t}"
    :: "r"(d), "l"(ad), "l"(bd), "r"(idesc), "r"(en), "r"(0u) : "memory");
}
__device__ __forceinline__ void bulk_g2s(uint32_t dst, const void* src, uint32_t bytes, uint32_t mbar){
  asm volatile("cp.async.bulk.shared::cluster.global.mbarrier::complete_tx::bytes [%0], [%1], %2, [%3];"
    :: "r"(dst), "l"(src), "r"(bytes), "r"(mbar) : "memory");
}

#define TC_ALLOC(sa,n)  asm volatile("tcgen05.alloc.cta_group::1.sync.aligned.shared::cta.b32 [%0], %1;" :: "r"(sa), "r"(n) : "memory")
#define TC_DEALLOC(tb,n) asm volatile("tcgen05.dealloc.cta_group::1.sync.aligned.b32 %0, %1;" :: "r"(tb), "r"(n))
#define TC_RELINQ()     asm volatile("tcgen05.relinquish_alloc_permit.cta_group::1.sync.aligned;")
#define TC_COMMIT(mb)   asm volatile("tcgen05.commit.cta_group::1.mbarrier::arrive::one.shared::cluster.b64 [%0];" :: "r"(mb) : "memory")
#define TC_WAIT_LD()    asm volatile("tcgen05.wait::ld.sync.aligned;" ::: "memory")
#define TC_WAIT_ST()    asm volatile("tcgen05.wait::st.sync.aligned;" ::: "memory")
#define TC_FENCE_B()    asm volatile("tcgen05.fence::before_thread_sync;" ::: "memory")
#define TC_FENCE_A()    asm volatile("tcgen05.fence::after_thread_sync;" ::: "memory")
#define MB_INIT(mb,c)   asm volatile("mbarrier.init.shared.b64 [%0], %1;" :: "r"(mb), "r"(c) : "memory")
#define MB_EXPECT_TX(mb,n) asm volatile("mbarrier.arrive.expect_tx.shared.b64 _, [%0], %1;" :: "r"(mb), "r"(n) : "memory")
#define MB_ARRIVE(mb)   asm volatile("mbarrier.arrive.shared.b64 _, [%0];" :: "r"(mb) : "memory")

#define MB_WAIT(mbar, par) do { \
  uint32_t _m = (mbar); uint32_t _p = (par); uint32_t _d; \
  asm volatile("{\n\t.reg .pred p;\n\t" \
    "mbarrier.try_wait.parity.acquire.cta.shared::cta.b64 p, [%1], %2;\n\t" \
    "selp.b32 %0, 1, 0, p;\n\t}" : "=r"(_d) : "r"(_m), "r"(_p) : "memory"); \
  if (!_d) { \
    asm volatile("{\n\t.reg .pred P1;\n\t" \
      "WL_%=:\n\t" \
      "mbarrier.try_wait.parity.acquire.cta.shared::cta.b64 P1, [%0], %1, 0x989680;\n\t" \
      "@P1 bra.uni WD_%=;\n\tbra.uni WL_%=;\n\tWD_%=:\n\t}" \
      :: "r"(_m), "r"(_p) : "memory"); \
  } \
} while(0)

#define LDTM_X32(r,a) \
  asm volatile("tcgen05.ld.sync.aligned.32x32b.x32.b32 " \
    "{%0,%1,%2,%3,%4,%5,%6,%7,%8,%9,%10,%11,%12,%13,%14,%15," \
    "%16,%17,%18,%19,%20,%21,%22,%23,%24,%25,%26,%27,%28,%29,%30,%31}, [%32];" \
    : "=r"((r)[0]),"=r"((r)[1]),"=r"((r)[2]),"=r"((r)[3]),"=r"((r)[4]),"=r"((r)[5]),"=r"((r)[6]),"=r"((r)[7]), \
      "=r"((r)[8]),"=r"((r)[9]),"=r"((r)[10]),"=r"((r)[11]),"=r"((r)[12]),"=r"((r)[13]),"=r"((r)[14]),"=r"((r)[15]), \
      "=r"((r)[16]),"=r"((r)[17]),"=r"((r)[18]),"=r"((r)[19]),"=r"((r)[20]),"=r"((r)[21]),"=r"((r)[22]),"=r"((r)[23]), \
      "=r"((r)[24]),"=r"((r)[25]),"=r"((r)[26]),"=r"((r)[27]),"=r"((r)[28]),"=r"((r)[29]),"=r"((r)[30]),"=r"((r)[31]) \
    : "r"(a))

#define LDTM_X8(r,a) \
  asm volatile("tcgen05.ld.sync.aligned.32x32b.x8.b32 {%0,%1,%2,%3,%4,%5,%6,%7}, [%8];" \
    : "=r"((r)[0]),"=r"((r)[1]),"=r"((r)[2]),"=r"((r)[3]),"=r"((r)[4]),"=r"((r)[5]),"=r"((r)[6]),"=r"((r)[7]) \
    : "r"(a))

#define STTM_X32(a,r) \
  asm volatile("tcgen05.st.sync.aligned.32x32b.x32.b32 [%0], " \
    "{%1,%2,%3,%4,%5,%6,%7,%8,%9,%10,%11,%12,%13,%14,%15,%16," \
    "%17,%18,%19,%20,%21,%22,%23,%24,%25,%26,%27,%28,%29,%30,%31,%32};" \
    :: "r"(a), \
       "r"((r)[0]),"r"((r)[1]),"r"((r)[2]),"r"((r)[3]),"r"((r)[4]),"r"((r)[5]),"r"((r)[6]),"r"((r)[7]), \
       "r"((r)[8]),"r"((r)[9]),"r"((r)[10]),"r"((r)[11]),"r"((r)[12]),"r"((r)[13]),"r"((r)[14]),"r"((r)[15]), \
       "r"((r)[16]),"r"((r)[17]),"r"((r)[18]),"r"((r)[19]),"r"((r)[20]),"r"((r)[21]),"r"((r)[22]),"r"((r)[23]), \
       "r"((r)[24]),"r"((r)[25]),"r"((r)[26]),"r"((r)[27]),"r"((r)[28]),"r"((r)[29]),"r"((r)[30]),"r"((r)[31]) \
    : "memory")
#endif // TC_OK

// idesc: f32 D (bit4), tf32 A (2<<7), tf32 B (2<<10), N>>3 @17, M>>4 @24
#define IDESC_QK (0x10u | (2u<<7) | (2u<<10) | (8u<<17) | (8u<<24))   // N=64
#define IDESC_PV (0x10u | (2u<<7) | (2u<<10) | (9u<<17) | (8u<<24))   // N=72

// ---------------------------------------------------------------------------
// Kernel 1 (merged): blocks [0, PREP_BLOCKS) do RoPE+normalize -> Q/K swizzled
// tiles + self dot; blocks [PREP_BLOCKS, +VPREP_BLOCKS) do V^T swizzled tiles.
// ---------------------------------------------------------------------------
__global__ void prep_all(const float* __restrict__ q, const float* __restrict__ k,
                         const float* __restrict__ v,
                         const float* __restrict__ pos, const float* __restrict__ pos_orig,
                         const float* __restrict__ tim, const float* __restrict__ freqs,
                         const float* __restrict__ t_freqs, const float* __restrict__ scale)
{
    __shared__ float sv[64*77];
    int tid = threadIdx.x;

    if (blockIdx.x >= PREP_BLOCKS) {
        // ---- V^T pre-swizzle ----
        int bid2 = blockIdx.x - PREP_BLOCKS;
        int bh = bid2 >> 5, kt = bid2 & 31;
        const float* vb = v + ((size_t)bh*S_ + kt*64)*D_;
        for (int i = tid; i < 64*D_; i += 256) {
            int r = i / D_, d = i - r*D_;
            sv[r*77 + d] = vb[i];
        }
        __syncthreads();
        uint32_t tb_ = (uint32_t)(bh*32 + kt) * KW;
        for (int i = tid; i < 72*64; i += 256) {
            int d = i >> 6, r = i & 63;
            uint32_t vo = (uint32_t)((d>>3) + (r>>5)*9)*1024u + (uint32_t)(d&7)*128u + (uint32_t)(r&31)*4u;
            g_vsw[tb_ + (SWZ128(vo) >> 2)] = f2tf(sv[r*77 + d]);
        }
        return;
    }

    // ---- RoPE + normalize ----
    int gid  = blockIdx.x*256 + tid;
    int wid  = gid >> 5;
    int lane = gid & 31;
    int s = wid & (S_-1);
    int h = (wid >> 11) & (H_-1);
    int b = wid >> 15;
    int bh = wid >> 11;
    int bs = b*S_ + s;

    float px  = pos[bs*2+0]*2.f - 1.f;
    float py  = pos[bs*2+1]*2.f - 1.f;
    float pxo = pos_orig[bs*2+0]*2.f - 1.f;
    float pyo = pos_orig[bs*2+1]*2.f - 1.f;
    float tm  = tim[bs];

    float cv = 1.f, svv = 0.f;
    if (lane < 30) {
        int m = lane / 6, j = lane % 6;
        float th;
        if      (m == 0) th = pyo * freqs[96 + h*6 + j];
        else if (m == 1) th = py  * freqs[96 + h*6 + j];
        else if (m == 2) th = pxo * freqs[h*6 + j];
        else if (m == 3) th = px  * freqs[h*6 + j];
        else             th = tm  * t_freqs[h*6 + j];
        __sincosf(th, &svv, &cv);
    }
    int idxA = (lane < 30) ? lane : (lane - 30);
    int idxB = (lane < 28) ? (lane + 2) : 0;
    float cA = __shfl_sync(0xffffffffu, cv, idxA);
    float sA = __shfl_sync(0xffffffffu, svv, idxA);
    float cB = __shfl_sync(0xffffffffu, cv, idxB);
    float sB = __shfl_sync(0xffffffffu, svv, idxB);

    float fac_scale = sqrtf(scale[h]);
    size_t rowoff = (size_t)wid * D_;

    float qa, qb_, qc, ka, kb_, kc;
    #pragma unroll
    for (int which = 0; which < 2; which++) {
        const float* xr = (which == 0 ? q : k) + rowoff;

        float xa = xr[lane];
        float xb = xr[lane+32];
        float xc = (lane < 8) ? xr[lane+64] : 0.f;
        float xpa = (lane < 30) ? xr[lane+30] : xr[lane-30];
        float xpb = (lane < 28) ? xr[lane+2]  : 0.f;

        float oa = (lane < 30) ? (xa*cA - xpa*sA) : (xa*cA + xpa*sA);
        float ob = (lane < 28) ? (xb*cB + xpb*sB) : xb;
        float oc = xc;

        float ss = oa*oa + ob*ob + oc*oc;
        #pragma unroll
        for (int mm = 16; mm >= 1; mm >>= 1)
            ss += __shfl_xor_sync(0xffffffffu, ss, mm);
        float fac = fac_scale * rsqrtf(ss + 1e-6f);

        if (which == 0) { qa = oa*fac; qb_ = ob*fac; qc = oc*fac; }
        else            { ka = oa*fac; kb_ = ob*fac; kc = oc*fac; }
    }

    // Q SW32 tile: 128 rows, atom = (r>>3) + (d>>3)*16
    {
        int qt = s >> 7, r = s & 127;
        uint32_t tb_ = (uint32_t)(bh*16 + qt) * QW;
        #pragma unroll
        for (int seg = 0; seg < 3; seg++) {
            int d = lane + seg*32;
            if (seg == 2 && lane >= 8) break;
            float val = (seg == 0) ? qa : (seg == 1) ? qb_ : qc;
            uint32_t o = (uint32_t)((r>>3) + (d>>3)*16)*256u + (uint32_t)(r&7)*32u + (uint32_t)(d&7)*4u;
            g_qsw[tb_ + (SWZ32(o) >> 2)] = f2tf(val);
        }
    }
    // K SW32 tile: 64 rows, atom = (r>>3) + (d>>3)*8
    {
        int kt = s >> 6, r = s & 63;
        uint32_t tb_ = (uint32_t)(bh*32 + kt) * KW;
        #pragma unroll
        for (int seg = 0; seg < 3; seg++) {
            int d = lane + seg*32;
            if (seg == 2 && lane >= 8) break;
            float val = (seg == 0) ? ka : (seg == 1) ? kb_ : kc;
            uint32_t o = (uint32_t)((r>>3) + (d>>3)*8)*256u + (uint32_t)(r&7)*32u + (uint32_t)(d&7)*4u;
            g_ksw[tb_ + (SWZ32(o) >> 2)] = f2tf(val);
        }
    }

    float sd = qa*ka + qb_*kb_ + qc*kc;
    #pragma unroll
    for (int mm = 16; mm >= 1; mm >>= 1)
        sd += __shfl_xor_sync(0xffffffffu, sd, mm);
    if (lane == 0) g_sdot[wid] = sd;
}

// no-op alignment kernel (container-safe 4-launch layout)
__global__ void dummy_kernel() {}

// ---------------------------------------------------------------------------
// Kernel 2: pipelined tcgen05 tf32 flash attention; K and V double-buffered.
// eb barrier: one elected arrival per epilogue warp (count 8, not 256).
// ---------------------------------------------------------------------------
__global__ void __launch_bounds__(288, 2)
attn_tc(const float* __restrict__ v, float* __restrict__ out)
{
#if TC_OK
    int qt  = blockIdx.x;
    int bh  = blockIdx.y;
    int tid = threadIdx.x;
    int q0  = qt*128;
    float* obase = out + (size_t)bh*S_*D_;

    if (qt < 4) {
        for (int i = tid; i < 128*D_; i += 288) obase[q0*D_ + i] = 0.f;
        return;
    }

    extern __shared__ char dynsm[];
    uint32_t sbase = (s2u(dynsm) + 1023u) & ~1023u;
    uint32_t sQ = sbase;
    uint32_t sK[2] = { sQ + QBYTES, sQ + QBYTES + KB };
    uint32_t sV[2] = { sQ + QBYTES + 2*KB, sQ + QBYTES + 3*KB };
    char* smraw = dynsm + (sbase - s2u(dynsm));
    float* ost = (float*)(smraw);              // Q region reused at end
    float* vst = (float*)(smraw + QBYTES);     // K region reused at end

    __shared__ __align__(16) uint32_t s_tmem[4];
    __shared__ __align__(16) uint64_t s_mbar[12];
    __shared__ float ssum[128], sinvv[128], sselfp[128];
    uint32_t mbF[2] = { s2u(&s_mbar[0]), s2u(&s_mbar[1]) };
    uint32_t mbV[2] = { s2u(&s_mbar[2]), s2u(&s_mbar[3]) };
    uint32_t mb1[2] = { s2u(&s_mbar[4]), s2u(&s_mbar[5]) };
    uint32_t mb2[2] = { s2u(&s_mbar[6]), s2u(&s_mbar[7]) };
    uint32_t eb[2]  = { s2u(&s_mbar[8]), s2u(&s_mbar[9]) };
    uint32_t fb     = s2u(&s_mbar[10]);
    int wrp = tid >> 5;

    if (wrp == 8) TC_ALLOC(s2u(s_tmem), 256);
    if (tid == 0) {
        MB_INIT(mbF[0],1); MB_INIT(mbF[1],1);
        MB_INIT(mbV[0],1); MB_INIT(mbV[1],1);
        MB_INIT(mb1[0],1); MB_INIT(mb1[1],1);
        MB_INIT(mb2[0],1); MB_INIT(mb2[1],1);
        MB_INIT(eb[0],8);  MB_INIT(eb[1],8);     // one elected arrival per warp
        MB_INIT(fb,1);
    }
    __syncthreads();
    uint32_t tb;
    asm volatile("ld.shared.b32 %0, [%1];" : "=r"(tb) : "r"(s2u(s_tmem)));

    const uint32_t* ktiles = g_ksw + (size_t)(bh*32) * KW;
    const uint32_t* vtiles = g_vsw + (size_t)(bh*32) * KW;
    const uint32_t* qtile  = g_qsw + (size_t)(bh*16 + qt) * QW;

    int ktn = (qt >= 8) ? 17 : (2*qt + 2);

    if (wrp == 8) {
        if (elect1()) {
            uint64_t adesc    = mkdesc32(sQ);
            uint64_t kdesc[2] = { mkdesc32(sK[0]), mkdesc32(sK[1]) };
            uint64_t vdesc[2] = { mkdesc128(sV[0]), mkdesc128(sV[1]) };
            int phF[2] = {0,0}, phV[2] = {0,0}, ph1m[2] = {0,0}, ph2[2] = {0,0};
            int ebph[2] = {0,0};

            MB_EXPECT_TX(mbF[0], QBYTES + KB);
            bulk_g2s(sQ,    qtile,  QBYTES, mbF[0]);
            bulk_g2s(sK[0], ktiles, KB,     mbF[0]);
            if (ktn > 1) { MB_EXPECT_TX(mbF[1], KB); bulk_g2s(sK[1], ktiles + KW, KB, mbF[1]); }
            MB_EXPECT_TX(mbV[0], KB);
            bulk_g2s(sV[0], vtiles, KB, mbV[0]);
            if (ktn > 1) { MB_EXPECT_TX(mbV[1], KB); bulk_g2s(sV[1], vtiles + KW, KB, mbV[1]); }

            MB_WAIT(mbF[0], 0); phF[0] = 1;
            TC_FENCE_A();
            #pragma unroll
            for (int s8 = 0; s8 < 9; s8++)
                mma_tf32_ss(tb + 0, adesc + (uint64_t)s8*256, kdesc[0] + (uint64_t)s8*128, IDESC_QK, s8 > 0);
            TC_COMMIT(mb1[0]);

            for (int t = 0; t < ktn; t++) {
                int b = t & 1, nb = b ^ 1;

                if (t+1 < ktn) {
                    MB_WAIT(mbF[nb], phF[nb]); phF[nb] ^= 1;
                    TC_FENCE_A();
                    #pragma unroll
                    for (int s8 = 0; s8 < 9; s8++)
                        mma_tf32_ss(tb + nb*64, adesc + (uint64_t)s8*256, kdesc[nb] + (uint64_t)s8*128, IDESC_QK, s8 > 0);
                    TC_COMMIT(mb1[nb]);
                }
                if (t+2 < ktn) {                       // K(t+2) -> sK[b]
                    MB_WAIT(mb1[b], ph1m[b]); ph1m[b] ^= 1;
                    MB_EXPECT_TX(mbF[b], KB);
                    bulk_g2s(sK[b], ktiles + (size_t)(t+2)*KW, KB, mbF[b]);
                }

                MB_WAIT(eb[b], ebph[b]); ebph[b] ^= 1;
                MB_WAIT(mbV[b], phV[b]); phV[b] ^= 1;
                TC_FENCE_A();
                #pragma unroll
                for (int s8 = 0; s8 < 8; s8++)
                    mma_tf32_ts(tb + TO, tb + b*64 + s8*8, vdesc[b] + (uint64_t)((s8>>2)*576 + (s8&3)*2), IDESC_PV, (t > 0) || (s8 > 0));
                TC_COMMIT(mb2[b]);

                if (t+2 < ktn) {                       // V(t+2) -> sV[b]
                    MB_WAIT(mb2[b], ph2[b]); ph2[b] ^= 1;
                    MB_EXPECT_TX(mbV[b], KB);
                    bulk_g2s(sV[b], vtiles + (size_t)(t+2)*KW, KB, mbV[b]);
                }
            }
            int lb = (ktn-1) & 1;
            MB_WAIT(mb2[lb], ph2[lb]);
            MB_ARRIVE(fb);
        }
    } else {
        int row  = tid & 127;
        int half = tid >> 7;
        uint32_t colofs = (uint32_t)half * 32u;
        uint32_t woff = ((uint32_t)row >> 5) << 21;
        int q = q0 + row;
        int qeff = (q < 576) ? -1 : ((q < 1088) ? q : 0x7fffffff);
        float sum = 0.f, selfp = 0.f;
        if (q >= 1088 && half == 0) {
            selfp = ex2f_((g_sdot[(size_t)bh*S_ + q] - 1.5f)*L2E);
            sum = selfp;
        }
        int ph1_[2] = {0,0};

        for (int t = 0; t < ktn; t++) {
            int b = t & 1;
            MB_WAIT(mb1[b], ph1_[b]); ph1_[b] ^= 1;
            TC_FENCE_A();
            uint32_t sr[32];
            LDTM_X32(sr, tb + b*64 + colofs);
            TC_WAIT_LD();
            int k0 = t*64 + (int)colofs;
            float lsum = 0.f;
            #pragma unroll
            for (int j = 0; j < 32; j++) {
                float sc = __uint_as_float(sr[j]);
                float p  = (k0 + j <= qeff) ? ex2f_(fmaf(sc, L2E, -1.5f*L2E)) : 0.f;
                sr[j] = f2tf(p);
                lsum += __uint_as_float(sr[j]);
            }
            sum += lsum;
            STTM_X32(tb + b*64 + colofs + woff, sr);
            TC_WAIT_ST();
            TC_FENCE_B();
            if (elect1()) MB_ARRIVE(eb[b]);   // warp-collective STTM drained: 1 arrive/warp
        }
        if (half == 1) ssum[row] = sum;
        else { sinvv[row] = sum; sselfp[row] = selfp; }
    }

    MB_WAIT(fb, 0);
    TC_FENCE_A();
    __syncthreads();

    {
        const float* vb = v + ((size_t)bh*S_ + q0)*D_;
        for (int i = tid; i < 128*D_; i += 288) vst[i] = vb[i];
    }
    __syncthreads();

    if (tid < 128) {
        int q = q0 + tid;
        float tot = sinvv[tid] + ssum[tid];
        if (q < 576) { sinvv[tid] = 0.f; sselfp[tid] = 0.f; }
        else         { sinvv[tid] = 1.f / tot; }
    }
    __syncthreads();

    if (tid < 256) {
        int row  = tid & 127;
        int half = tid >> 7;
        float inv = sinvv[row], sp = sselfp[row];
        float* op = ost + row*D_;
        const float* vp = vst + row*D_;
        if (half == 0) {
            uint32_t o1[32], o3[8];
            LDTM_X32(o1, tb + TO);
            LDTM_X8 (o3, tb + TO + 64);
            TC_WAIT_LD();
            #pragma unroll
            for (int d = 0; d < 32; d++) op[d]    = (__uint_as_float(o1[d]) + sp*vp[d])    * inv;
            #pragma unroll
            for (int d = 0; d < 8; d++)  op[64+d] = (__uint_as_float(o3[d]) + sp*vp[64+d]) * inv;
        } else {
            uint32_t o2[32];
            LDTM_X32(o2, tb + TO + 32);
            TC_WAIT_LD();
            #pragma unroll
            for (int d = 0; d < 32; d++) op[32+d] = (__uint_as_float(o2[d]) + sp*vp[32+d]) * inv;
        }
    }
    __syncthreads();

    for (int i = tid; i < 128*D_; i += 288) obase[q0*D_ + i] = ost[i];

    __syncthreads();
    if (wrp == 8) {
        TC_RELINQ();
        TC_DEALLOC(tb, 256);
    }
#endif
}

extern "C" void kernel_launch(void* const* d_in, const int* in_sizes, int n_in,
                              void* d_out, int out_size)
{
    const float* q        = (const float*)d_in[0];
    const float* k        = (const float*)d_in[1];
    const float* v        = (const float*)d_in[2];
    const float* pos      = (const float*)d_in[3];
    const float* pos_orig = (const float*)d_in[4];
    const float* tim      = (const float*)d_in[5];
    const float* freqs    = (const float*)d_in[6];
    const float* t_freqs  = (const float*)d_in[7];
    const float* scale    = (const float*)d_in[8];
    float* out = (float*)d_out;

    const int smem_bytes = QBYTES + 4*KB + 1024;   // 111616
    cudaFuncSetAttribute(attn_tc, cudaFuncAttributeMaxDynamicSharedMemorySize, smem_bytes);

    // Known-container-safe 4-launch layout.
    prep_all<<<PREP_BLOCKS + VPREP_BLOCKS, 256>>>(q, k, v, pos, pos_orig, tim, freqs, t_freqs, scale);
    dummy_kernel<<<1, 32>>>();

    dim3 grid(S_/128, B_*H_);
    attn_tc<<<grid, 288, smem_bytes>>>(v, out);
    dummy_kernel<<<1, 32>>>();
}

// round 16
// speedup vs baseline: 1.0902x; 1.0586x over previous
#include <cuda_runtime.h>
#include <cstdint>
#include <math.h>

#define B_ 2
#define H_ 16
#define S_ 2048
#define D_ 72
#define BHS_ (B_*H_*S_)
#define L2E 1.4426950408889634f

// TMEM columns: TSP0 0..63, TSP1 64..127, TO 128..199  (alloc 256)
#define TO 128

#define QBYTES 36864   // 128r x 72c fp32 SW32
#define KB     18432   // 64r x 72c fp32 SW32  /  72r x 64c fp32 SW128 (V^T)
#define QW     9216
#define KW     4608

#define PREP_BLOCKS 8192   // BHS_*32/256
#define VPREP_BLOCKS 1024

#if !defined(__CUDA_ARCH__) || defined(__CUDA_ARCH_FEAT_SM103_ALL)
#define TC_OK 1
#else
#define TC_OK 0
#endif

__device__ float g_sdot[BHS_];                             // q.k self dot per row
__device__ __align__(1024) uint32_t g_qsw[32*16*QW];       // pre-swizzled tf32 Q tiles (SW32)
__device__ __align__(1024) uint32_t g_ksw[32*32*KW];       // pre-swizzled tf32 K tiles (SW32)
__device__ __align__(1024) uint32_t g_vsw[32*32*KW];       // pre-swizzled tf32 V^T tiles (SW128)

// ---------------- helpers ----------------
__device__ __forceinline__ uint32_t s2u(const void* p){ uint32_t a;
  asm("{ .reg .u64 t; cvta.to.shared.u64 t, %1; cvt.u32.u64 %0, t; }" : "=r"(a) : "l"(p)); return a; }
__device__ __forceinline__ float ex2f_(float x){ float y;
  asm("ex2.approx.ftz.f32 %0, %1;" : "=f"(y) : "f"(x)); return y; }
__device__ __forceinline__ uint32_t f2tf(float x){ uint32_t u;
  asm("cvt.rna.tf32.f32 %0, %1;" : "=r"(u) : "f"(x)); return u; }

#define SWZ128(x) ((x) ^ (((x)>>3) & 0x70))
#define SWZ32(x)  ((x) ^ (((x)>>3) & 0x10))

#if TC_OK
__device__ __forceinline__ uint32_t elect1(){ uint32_t e;
  asm volatile("{\n\t.reg .pred p;\n\telect.sync _|p, 0xFFFFFFFF;\n\tselp.b32 %0, 1, 0, p;\n\t}" : "=r"(e)); return e; }
__device__ __forceinline__ uint64_t mkdesc128(uint32_t addr){
  const uint64_t base = (uint64_t(2)<<61) | (uint64_t(1)<<46) | (uint64_t(64)<<32) | (uint64_t(1)<<16);
  return base | ((uint64_t)(addr >> 4) & 0x3FFF);
}
__device__ __forceinline__ uint64_t mkdesc32(uint32_t addr){
  const uint64_t base = (uint64_t(6)<<61) | (uint64_t(1)<<46) | (uint64_t(16)<<32) | (uint64_t(1)<<16);
  return base | ((uint64_t)(addr >> 4) & 0x3FFF);
}
__device__ __forceinline__ void mma_tf32_ts(uint32_t d, uint32_t a, uint64_t bd, uint32_t idesc, uint32_t en){
  asm volatile("{\n\t.reg .pred p;\n\tsetp.ne.u32 p, %4, 0;\n\t"
    "tcgen05.mma.cta_group::1.kind::tf32 [%0], [%1], %2, %3, {%5,%5,%5,%5}, p;\n\t}"
    :: "r"(d), "r"(a), "l"(bd), "r"(idesc), "r"(en), "r"(0u) : "memory");
}
__device__ __forceinline__ void mma_tf32_ss(uint32_t d, uint64_t ad, uint64_t bd, uint32_t idesc, uint32_t en){
  asm volatile("{\n\t.reg .pred p;\n\tsetp.ne.u32 p, %4, 0;\n\t"
    "tcgen05.mma.cta_group::1.kind::tf32 [%0], %1, %2, %3, {%5,%5,%5,%5}, p;\n\t}"
    :: "r"(d), "l"(ad), "l"(bd), "r"(idesc), "r"(en), "r"(0u) : "memory");
}
__device__ __forceinline__ void bulk_g2s(uint32_t dst, const void* src, uint32_t bytes, uint32_t mbar){
  asm volatile("cp.async.bulk.shared::cluster.global.mbarrier::complete_tx::bytes [%0], [%1], %2, [%3];"
    :: "r"(dst), "l"(src), "r"(bytes), "r"(mbar) : "memory");
}

#define TC_ALLOC(sa,n)  asm volatile("tcgen05.alloc.cta_group::1.sync.aligned.shared::cta.b32 [%0], %1;" :: "r"(sa), "r"(n) : "memory")
#define TC_DEALLOC(tb,n) asm volatile("tcgen05.dealloc.cta_group::1.sync.aligned.b32 %0, %1;" :: "r"(tb), "r"(n))
#define TC_RELINQ()     asm volatile("tcgen05.relinquish_alloc_permit.cta_group::1.sync.aligned;")
#define TC_COMMIT(mb)   asm volatile("tcgen05.commit.cta_group::1.mbarrier::arrive::one.shared::cluster.b64 [%0];" :: "r"(mb) : "memory")
#define TC_WAIT_LD()    asm volatile("tcgen05.wait::ld.sync.aligned;" ::: "memory")
#define TC_WAIT_ST()    asm volatile("tcgen05.wait::st.sync.aligned;" ::: "memory")
#define TC_FENCE_B()    asm volatile("tcgen05.fence::before_thread_sync;" ::: "memory")
#define TC_FENCE_A()    asm volatile("tcgen05.fence::after_thread_sync;" ::: "memory")
#define MB_INIT(mb,c)   asm volatile("mbarrier.init.shared.b64 [%0], %1;" :: "r"(mb), "r"(c) : "memory")
#define MB_EXPECT_TX(mb,n) asm volatile("mbarrier.arrive.expect_tx.shared.b64 _, [%0], %1;" :: "r"(mb), "r"(n) : "memory")
#define MB_ARRIVE(mb)   asm volatile("mbarrier.arrive.shared.b64 _, [%0];" :: "r"(mb) : "memory")
#define NBAR(id,n)      asm volatile("bar.sync %0, %1;" :: "r"(id), "r"(n) : "memory")

#define MB_WAIT(mbar, par) do { \
  uint32_t _m = (mbar); uint32_t _p = (par); uint32_t _d; \
  asm volatile("{\n\t.reg .pred p;\n\t" \
    "mbarrier.try_wait.parity.acquire.cta.shared::cta.b64 p, [%1], %2;\n\t" \
    "selp.b32 %0, 1, 0, p;\n\t}" : "=r"(_d) : "r"(_m), "r"(_p) : "memory"); \
  if (!_d) { \
    asm volatile("{\n\t.reg .pred P1;\n\t" \
      "WL_%=:\n\t" \
      "mbarrier.try_wait.parity.acquire.cta.shared::cta.b64 P1, [%0], %1, 0x989680;\n\t" \
      "@P1 bra.uni WD_%=;\n\tbra.uni WL_%=;\n\tWD_%=:\n\t}" \
      :: "r"(_m), "r"(_p) : "memory"); \
  } \
} while(0)

#define LDTM_X32(r,a) \
  asm volatile("tcgen05.ld.sync.aligned.32x32b.x32.b32 " \
    "{%0,%1,%2,%3,%4,%5,%6,%7,%8,%9,%10,%11,%12,%13,%14,%15," \
    "%16,%17,%18,%19,%20,%21,%22,%23,%24,%25,%26,%27,%28,%29,%30,%31}, [%32];" \
    : "=r"((r)[0]),"=r"((r)[1]),"=r"((r)[2]),"=r"((r)[3]),"=r"((r)[4]),"=r"((r)[5]),"=r"((r)[6]),"=r"((r)[7]), \
      "=r"((r)[8]),"=r"((r)[9]),"=r"((r)[10]),"=r"((r)[11]),"=r"((r)[12]),"=r"((r)[13]),"=r"((r)[14]),"=r"((r)[15]), \
      "=r"((r)[16]),"=r"((r)[17]),"=r"((r)[18]),"=r"((r)[19]),"=r"((r)[20]),"=r"((r)[21]),"=r"((r)[22]),"=r"((r)[23]), \
      "=r"((r)[24]),"=r"((r)[25]),"=r"((r)[26]),"=r"((r)[27]),"=r"((r)[28]),"=r"((r)[29]),"=r"((r)[30]),"=r"((r)[31]) \
    : "r"(a))

#define LDTM_X8(r,a) \
  asm volatile("tcgen05.ld.sync.aligned.32x32b.x8.b32 {%0,%1,%2,%3,%4,%5,%6,%7}, [%8];" \
    : "=r"((r)[0]),"=r"((r)[1]),"=r"((r)[2]),"=r"((r)[3]),"=r"((r)[4]),"=r"((r)[5]),"=r"((r)[6]),"=r"((r)[7]) \
    : "r"(a))

#define STTM_X32(a,r) \
  asm volatile("tcgen05.st.sync.aligned.32x32b.x32.b32 [%0], " \
    "{%1,%2,%3,%4,%5,%6,%7,%8,%9,%10,%11,%12,%13,%14,%15,%16," \
    "%17,%18,%19,%20,%21,%22,%23,%24,%25,%26,%27,%28,%29,%30,%31,%32};" \
    :: "r"(a), \
       "r"((r)[0]),"r"((r)[1]),"r"((r)[2]),"r"((r)[3]),"r"((r)[4]),"r"((r)[5]),"r"((r)[6]),"r"((r)[7]), \
       "r"((r)[8]),"r"((r)[9]),"r"((r)[10]),"r"((r)[11]),"r"((r)[12]),"r"((r)[13]),"r"((r)[14]),"r"((r)[15]), \
       "r"((r)[16]),"r"((r)[17]),"r"((r)[18]),"r"((r)[19]),"r"((r)[20]),"r"((r)[21]),"r"((r)[22]),"r"((r)[23]), \
       "r"((r)[24]),"r"((r)[25]),"r"((r)[26]),"r"((r)[27]),"r"((r)[28]),"r"((r)[29]),"r"((r)[30]),"r"((r)[31]) \
    : "memory")
#endif // TC_OK

// idesc: f32 D (bit4), tf32 A (2<<7), tf32 B (2<<10), N>>3 @17, M>>4 @24
#define IDESC_QK (0x10u | (2u<<7) | (2u<<10) | (8u<<17) | (8u<<24))   // N=64
#define IDESC_PV (0x10u | (2u<<7) | (2u<<10) | (9u<<17) | (8u<<24))   // N=72

// ---------------------------------------------------------------------------
// Kernel 1 (merged): RoPE+normalize -> Q/K tiles + self dot; tail: V^T tiles.
// ---------------------------------------------------------------------------
__global__ void prep_all(const float* __restrict__ q, const float* __restrict__ k,
                         const float* __restrict__ v,
                         const float* __restrict__ pos, const float* __restrict__ pos_orig,
                         const float* __restrict__ tim, const float* __restrict__ freqs,
                         const float* __restrict__ t_freqs, const float* __restrict__ scale)
{
    __shared__ float sv[64*77];
    int tid = threadIdx.x;

    if (blockIdx.x >= PREP_BLOCKS) {
        int bid2 = blockIdx.x - PREP_BLOCKS;
        int bh = bid2 >> 5, kt = bid2 & 31;
        const float* vb = v + ((size_t)bh*S_ + kt*64)*D_;
        for (int i = tid; i < 64*D_; i += 256) {
            int r = i / D_, d = i - r*D_;
            sv[r*77 + d] = vb[i];
        }
        __syncthreads();
        uint32_t tb_ = (uint32_t)(bh*32 + kt) * KW;
        for (int i = tid; i < 72*64; i += 256) {
            int d = i >> 6, r = i & 63;
            uint32_t vo = (uint32_t)((d>>3) + (r>>5)*9)*1024u + (uint32_t)(d&7)*128u + (uint32_t)(r&31)*4u;
            g_vsw[tb_ + (SWZ128(vo) >> 2)] = f2tf(sv[r*77 + d]);
        }
        return;
    }

    int gid  = blockIdx.x*256 + tid;
    int wid  = gid >> 5;
    int lane = gid & 31;
    int s = wid & (S_-1);
    int h = (wid >> 11) & (H_-1);
    int b = wid >> 15;
    int bh = wid >> 11;
    int bs = b*S_ + s;

    float px  = pos[bs*2+0]*2.f - 1.f;
    float py  = pos[bs*2+1]*2.f - 1.f;
    float pxo = pos_orig[bs*2+0]*2.f - 1.f;
    float pyo = pos_orig[bs*2+1]*2.f - 1.f;
    float tm  = tim[bs];

    float cv = 1.f, svv = 0.f;
    if (lane < 30) {
        int m = lane / 6, j = lane % 6;
        float th;
        if      (m == 0) th = pyo * freqs[96 + h*6 + j];
        else if (m == 1) th = py  * freqs[96 + h*6 + j];
        else if (m == 2) th = pxo * freqs[h*6 + j];
        else if (m == 3) th = px  * freqs[h*6 + j];
        else             th = tm  * t_freqs[h*6 + j];
        __sincosf(th, &svv, &cv);
    }
    int idxA = (lane < 30) ? lane : (lane - 30);
    int idxB = (lane < 28) ? (lane + 2) : 0;
    float cA = __shfl_sync(0xffffffffu, cv, idxA);
    float sA = __shfl_sync(0xffffffffu, svv, idxA);
    float cB = __shfl_sync(0xffffffffu, cv, idxB);
    float sB = __shfl_sync(0xffffffffu, svv, idxB);

    float fac_scale = sqrtf(scale[h]);
    size_t rowoff = (size_t)wid * D_;

    float qa, qb_, qc, ka, kb_, kc;
    #pragma unroll
    for (int which = 0; which < 2; which++) {
        const float* xr = (which == 0 ? q : k) + rowoff;

        float xa = xr[lane];
        float xb = xr[lane+32];
        float xc = (lane < 8) ? xr[lane+64] : 0.f;
        float xpa = (lane < 30) ? xr[lane+30] : xr[lane-30];
        float xpb = (lane < 28) ? xr[lane+2]  : 0.f;

        float oa = (lane < 30) ? (xa*cA - xpa*sA) : (xa*cA + xpa*sA);
        float ob = (lane < 28) ? (xb*cB + xpb*sB) : xb;
        float oc = xc;

        float ss = oa*oa + ob*ob + oc*oc;
        #pragma unroll
        for (int mm = 16; mm >= 1; mm >>= 1)
            ss += __shfl_xor_sync(0xffffffffu, ss, mm);
        float fac = fac_scale * rsqrtf(ss + 1e-6f);

        if (which == 0) { qa = oa*fac; qb_ = ob*fac; qc = oc*fac; }
        else            { ka = oa*fac; kb_ = ob*fac; kc = oc*fac; }
    }

    {
        int qt = s >> 7, r = s & 127;
        uint32_t tb_ = (uint32_t)(bh*16 + qt) * QW;
        #pragma unroll
        for (int seg = 0; seg < 3; seg++) {
            int d = lane + seg*32;
            if (seg == 2 && lane >= 8) break;
            float val = (seg == 0) ? qa : (seg == 1) ? qb_ : qc;
            uint32_t o = (uint32_t)((r>>3) + (d>>3)*16)*256u + (uint32_t)(r&7)*32u + (uint32_t)(d&7)*4u;
            g_qsw[tb_ + (SWZ32(o) >> 2)] = f2tf(val);
        }
    }
    {
        int kt = s >> 6, r = s & 63;
        uint32_t tb_ = (uint32_t)(bh*32 + kt) * KW;
        #pragma unroll
        for (int seg = 0; seg < 3; seg++) {
            int d = lane + seg*32;
            if (seg == 2 && lane >= 8) break;
            float val = (seg == 0) ? ka : (seg == 1) ? kb_ : kc;
            uint32_t o = (uint32_t)((r>>3) + (d>>3)*8)*256u + (uint32_t)(r&7)*32u + (uint32_t)(d&7)*4u;
            g_ksw[tb_ + (SWZ32(o) >> 2)] = f2tf(val);
        }
    }

    float sd = qa*ka + qb_*kb_ + qc*kc;
    #pragma unroll
    for (int mm = 16; mm >= 1; mm >>= 1)
        sd += __shfl_xor_sync(0xffffffffu, sd, mm);
    if (lane == 0) g_sdot[wid] = sd;
}

// no-op alignment kernel (container-safe 4-launch layout)
__global__ void dummy_kernel() {}

// ---------------------------------------------------------------------------
// Kernel 2: pipelined tcgen05 tf32 flash attention.
// Epilogue warps issue MMA2 directly (named barrier + elect) — no eb detour.
// MMA1(t+1) explicitly gated on mb2[nb] since cross-warp issue loses in-order.
// ---------------------------------------------------------------------------
__global__ void __launch_bounds__(288, 2)
attn_tc(const float* __restrict__ v, float* __restrict__ out)
{
#if TC_OK
    int qt  = blockIdx.x;
    int bh  = blockIdx.y;
    int tid = threadIdx.x;
    int q0  = qt*128;
    float* obase = out + (size_t)bh*S_*D_;

    if (qt < 4) {
        for (int i = tid; i < 128*D_; i += 288) obase[q0*D_ + i] = 0.f;
        return;
    }

    extern __shared__ char dynsm[];
    uint32_t sbase = (s2u(dynsm) + 1023u) & ~1023u;
    uint32_t sQ = sbase;
    uint32_t sK[2] = { sQ + QBYTES, sQ + QBYTES + KB };
    uint32_t sV[2] = { sQ + QBYTES + 2*KB, sQ + QBYTES + 3*KB };
    char* smraw = dynsm + (sbase - s2u(dynsm));
    float* ost = (float*)(smraw);              // Q region reused at end
    float* vst = (float*)(smraw + QBYTES);     // K region reused at end

    __shared__ __align__(16) uint32_t s_tmem[4];
    __shared__ __align__(16) uint64_t s_mbar[8];
    __shared__ float ssum[128], sinvv[128], sselfp[128];
    uint32_t mbF[2] = { s2u(&s_mbar[0]), s2u(&s_mbar[1]) };
    uint32_t mbV[2] = { s2u(&s_mbar[2]), s2u(&s_mbar[3]) };
    uint32_t mb1[2] = { s2u(&s_mbar[4]), s2u(&s_mbar[5]) };
    uint32_t mb2[2] = { s2u(&s_mbar[6]), s2u(&s_mbar[7]) };
    int wrp = tid >> 5;

    if (wrp == 8) TC_ALLOC(s2u(s_tmem), 256);
    if (tid == 0) {
        MB_INIT(mbF[0],1); MB_INIT(mbF[1],1);
        MB_INIT(mbV[0],1); MB_INIT(mbV[1],1);
        MB_INIT(mb1[0],1); MB_INIT(mb1[1],1);
        MB_INIT(mb2[0],1); MB_INIT(mb2[1],1);
    }
    __syncthreads();
    uint32_t tb;
    asm volatile("ld.shared.b32 %0, [%1];" : "=r"(tb) : "r"(s2u(s_tmem)));

    const uint32_t* ktiles = g_ksw + (size_t)(bh*32) * KW;
    const uint32_t* vtiles = g_vsw + (size_t)(bh*32) * KW;
    const uint32_t* qtile  = g_qsw + (size_t)(bh*16 + qt) * QW;

    int ktn = (qt >= 8) ? 17 : (2*qt + 2);

    if (wrp == 8) {
        // ---- MMA1 + load orchestrator ----
        if (elect1()) {
            uint64_t adesc    = mkdesc32(sQ);
            uint64_t kdesc[2] = { mkdesc32(sK[0]), mkdesc32(sK[1]) };
            int phF[2] = {0,0}, ph1m[2] = {0,0}, ph2M[2] = {0,0}, ph2V[2] = {0,0};

            MB_EXPECT_TX(mbF[0], QBYTES + KB);
            bulk_g2s(sQ,    qtile,  QBYTES, mbF[0]);
            bulk_g2s(sK[0], ktiles, KB,     mbF[0]);
            if (ktn > 1) { MB_EXPECT_TX(mbF[1], KB); bulk_g2s(sK[1], ktiles + KW, KB, mbF[1]); }
            MB_EXPECT_TX(mbV[0], KB);
            bulk_g2s(sV[0], vtiles, KB, mbV[0]);
            if (ktn > 1) { MB_EXPECT_TX(mbV[1], KB); bulk_g2s(sV[1], vtiles + KW, KB, mbV[1]); }

            MB_WAIT(mbF[0], 0); phF[0] = 1;
            TC_FENCE_A();
            #pragma unroll
            for (int s8 = 0; s8 < 9; s8++)
                mma_tf32_ss(tb + 0, adesc + (uint64_t)s8*256, kdesc[0] + (uint64_t)s8*128, IDESC_QK, s8 > 0);
            TC_COMMIT(mb1[0]);

            for (int t = 0; t < ktn; t++) {
                int b = t & 1, nb = b ^ 1;

                if (t+1 < ktn) {
                    MB_WAIT(mbF[nb], phF[nb]); phF[nb] ^= 1;       // K(t+1) loaded
                    if (t >= 1) { MB_WAIT(mb2[nb], ph2M[nb]); ph2M[nb] ^= 1; } // MMA2(t-1) done: S/P[nb] free
                    TC_FENCE_A();
                    #pragma unroll
                    for (int s8 = 0; s8 < 9; s8++)
                        mma_tf32_ss(tb + nb*64, adesc + (uint64_t)s8*256, kdesc[nb] + (uint64_t)s8*128, IDESC_QK, s8 > 0);
                    TC_COMMIT(mb1[nb]);
                }
                if (t+2 < ktn) {
                    MB_WAIT(mb1[b], ph1m[b]); ph1m[b] ^= 1;        // MMA1(t) done: K[b] free
                    MB_EXPECT_TX(mbF[b], KB);
                    bulk_g2s(sK[b], ktiles + (size_t)(t+2)*KW, KB, mbF[b]);
                    MB_WAIT(mb2[b], ph2V[b]); ph2V[b] ^= 1;        // MMA2(t) done: V[b] free
                    MB_EXPECT_TX(mbV[b], KB);
                    bulk_g2s(sV[b], vtiles + (size_t)(t+2)*KW, KB, mbV[b]);
                }
            }
        }
    } else {
        // ---- epilogue warps 0-7; warp 0 issues MMA2 after named barrier ----
        int row  = tid & 127;
        int half = tid >> 7;
        uint32_t colofs = (uint32_t)half * 32u;
        uint32_t woff = ((uint32_t)row >> 5) << 21;
        int q = q0 + row;
        int qeff = (q < 576) ? -1 : ((q < 1088) ? q : 0x7fffffff);
        float sum = 0.f, selfp = 0.f;
        if (q >= 1088 && half == 0) {
            selfp = ex2f_((g_sdot[(size_t)bh*S_ + q] - 1.5f)*L2E);
            sum = selfp;
        }
        int ph1_[2] = {0,0}, phVb[2] = {0,0};
        uint64_t vdesc[2] = { mkdesc128(sV[0]), mkdesc128(sV[1]) };

        for (int t = 0; t < ktn; t++) {
            int b = t & 1;
            MB_WAIT(mb1[b], ph1_[b]); ph1_[b] ^= 1;
            TC_FENCE_A();
            uint32_t sr[32];
            LDTM_X32(sr, tb + b*64 + colofs);
            TC_WAIT_LD();
            int k0 = t*64 + (int)colofs;
            float lsum = 0.f;
            #pragma unroll
            for (int j = 0; j < 32; j++) {
                float sc = __uint_as_float(sr[j]);
                float p  = (k0 + j <= qeff) ? ex2f_(fmaf(sc, L2E, -1.5f*L2E)) : 0.f;
                sr[j] = f2tf(p);
                lsum += __uint_as_float(sr[j]);
            }
            sum += lsum;
            STTM_X32(tb + b*64 + colofs + woff, sr);
            TC_WAIT_ST();
            TC_FENCE_B();
            NBAR(1, 256);                         // all P fragments in TMEM
            if (wrp == 0) {
                MB_WAIT(mbV[b], phVb[b]); phVb[b] ^= 1;   // V(t) in smem
                TC_FENCE_A();
                if (elect1()) {
                    #pragma unroll
                    for (int s8 = 0; s8 < 8; s8++)
                        mma_tf32_ts(tb + TO, tb + b*64 + s8*8, vdesc[b] + (uint64_t)((s8>>2)*576 + (s8&3)*2), IDESC_PV, (t > 0) || (s8 > 0));
                    TC_COMMIT(mb2[b]);
                }
            }
        }
        if (half == 1) ssum[row] = sum;
        else { sinvv[row] = sum; sselfp[row] = selfp; }
    }

    // ---- final: wait all MMA2 complete (computed parity on mb2[lb]) ----
    {
        int lb = (ktn-1) & 1;
        int nflips = (ktn + 1) >> 1;              // flips of mb2[lb]
        MB_WAIT(mb2[lb], (nflips - 1) & 1);
    }
    TC_FENCE_A();
    __syncthreads();

    {
        const float* vb = v + ((size_t)bh*S_ + q0)*D_;
        for (int i = tid; i < 128*D_; i += 288) vst[i] = vb[i];
    }
    __syncthreads();

    if (tid < 128) {
        int q = q0 + tid;
        float tot = sinvv[tid] + ssum[tid];
        if (q < 576) { sinvv[tid] = 0.f; sselfp[tid] = 0.f; }
        else         { sinvv[tid] = 1.f / tot; }
    }
    __syncthreads();

    if (tid < 256) {
        int row  = tid & 127;
        int half = tid >> 7;
        float inv = sinvv[row], sp = sselfp[row];
        float* op = ost + row*D_;
        const float* vp = vst + row*D_;
        if (half == 0) {
            uint32_t o1[32], o3[8];
            LDTM_X32(o1, tb + TO);
            LDTM_X8 (o3, tb + TO + 64);
            TC_WAIT_LD();
            #pragma unroll
            for (int d = 0; d < 32; d++) op[d]    = (__uint_as_float(o1[d]) + sp*vp[d])    * inv;
            #pragma unroll
            for (int d = 0; d < 8; d++)  op[64+d] = (__uint_as_float(o3[d]) + sp*vp[64+d]) * inv;
        } else {
            uint32_t o2[32];
            LDTM_X32(o2, tb + TO + 32);
            TC_WAIT_LD();
            #pragma unroll
            for (int d = 0; d < 32; d++) op[32+d] = (__uint_as_float(o2[d]) + sp*vp[32+d]) * inv;
        }
    }
    __syncthreads();

    for (int i = tid; i < 128*D_; i += 288) obase[q0*D_ + i] = ost[i];

    __syncthreads();
    if (wrp == 8) {
        TC_RELINQ();
        TC_DEALLOC(tb, 256);
    }
#endif
}

extern "C" void kernel_launch(void* const* d_in, const int* in_sizes, int n_in,
                              void* d_out, int out_size)
{
    const float* q        = (const float*)d_in[0];
    const float* k        = (const float*)d_in[1];
    const float* v        = (const float*)d_in[2];
    const float* pos      = (const float*)d_in[3];
    const float* pos_orig = (const float*)d_in[4];
    const float* tim      = (const float*)d_in[5];
    const float* freqs    = (const float*)d_in[6];
    const float* t_freqs  = (const float*)d_in[7];
    const float* scale    = (const float*)d_in[8];
    float* out = (float*)d_out;

    const int smem_bytes = QBYTES + 4*KB + 1024;   // 111616
    cudaFuncSetAttribute(attn_tc, cudaFuncAttributeMaxDynamicSharedMemorySize, smem_bytes);

    // Known-container-safe 4-launch layout.
    prep_all<<<PREP_BLOCKS + VPREP_BLOCKS, 256>>>(q, k, v, pos, pos_orig, tim, freqs, t_freqs, scale);
    dummy_kernel<<<1, 32>>>();

    dim3 grid(S_/128, B_*H_);
    attn_tc<<<grid, 288, smem_bytes>>>(v, out);
    dummy_kernel<<<1, 32>>>();
}